// round 5
// baseline (speedup 1.0000x reference)
#include <cuda_runtime.h>
#include <stdint.h>

// Shapes fixed by the problem definition.
#define V_TOK   50000
#define D_DIM   300
#define H_DIM   32
#define C_DIM   3
#define B_BATCH 2048
#define L_SEQ   200

// Scratch: T = emb_table @ W1, [V_TOK, H_DIM] fp32 (6.4 MB). __device__ global
// array (no dynamic allocation allowed anywhere).
__device__ float g_T[V_TOK * H_DIM];

// ---------------------------------------------------------------------------
// Kernel A: T[v][h] = sum_d emb[v][d] * W1[d][h]
// One thread per token. D processed in chunks of DC staged through SMEM
// (coalesced global loads), W1 chunk staged in SMEM (broadcast LDS.64 reads).
// Inner product uses packed fma.rn.f32x2 (2 MACs / instr on the fp32 pipe).
// ---------------------------------------------------------------------------
#define TOK_PER_CTA 128
#define DC 60   // 300 = 5 * 60

__global__ __launch_bounds__(TOK_PER_CTA)
void gemm_T_kernel(const float* __restrict__ emb, const float* __restrict__ W1) {
    __shared__ float a_stage[TOK_PER_CTA][DC + 1];        // +1 pad: conflict-free column reads
    __shared__ __align__(16) float w_stage[DC][H_DIM];    // rows 128B-aligned -> LDS.64 ok

    const int tid  = threadIdx.x;
    const int lane = tid & 31;
    const int wid  = tid >> 5;
    const int v0   = blockIdx.x * TOK_PER_CTA;
    const int v    = v0 + tid;

    // 16 packed f32x2 accumulators = 32 fp32 outputs
    unsigned long long acc[16];
#pragma unroll
    for (int i = 0; i < 16; i++) acc[i] = 0ULL;   // bit pattern of (0.0f, 0.0f)

    for (int d0 = 0; d0 < D_DIM; d0 += DC) {
        __syncthreads();
        // Stage W1 chunk: contiguous DC*H region starting at d0*H
        for (int i = tid; i < DC * H_DIM; i += TOK_PER_CTA)
            ((float*)w_stage)[i] = W1[d0 * H_DIM + i];
        // Stage emb rows for this CTA's tokens (coalesced: warp reads a row slice)
        for (int r = wid; r < TOK_PER_CTA; r += (TOK_PER_CTA / 32)) {
            int vv = v0 + r;
            if (vv < V_TOK) {
                for (int d = lane; d < DC; d += 32)
                    a_stage[r][d] = emb[vv * D_DIM + d0 + d];
            }
        }
        __syncthreads();

        if (v < V_TOK) {
#pragma unroll 4
            for (int k = 0; k < DC; k++) {
                float a = a_stage[tid][k];
                unsigned long long a2;
                asm("mov.b64 %0, {%1, %1};" : "=l"(a2) : "f"(a));
                const unsigned long long* wrow =
                    (const unsigned long long*)&w_stage[k][0];
#pragma unroll
                for (int hp = 0; hp < 16; hp++) {
                    asm("fma.rn.f32x2 %0, %1, %2, %0;"
                        : "+l"(acc[hp]) : "l"(a2), "l"(wrow[hp]));
                }
            }
        }
    }

    if (v < V_TOK) {
        float out[H_DIM];
#pragma unroll
        for (int hp = 0; hp < 16; hp++) {
            unsigned int lo, hi;
            asm("mov.b64 {%0, %1}, %2;" : "=r"(lo), "=r"(hi) : "l"(acc[hp]));
            out[2 * hp]     = __uint_as_float(lo);
            out[2 * hp + 1] = __uint_as_float(hi);
        }
        // Row is 128B and 16B-aligned: 8x STG.128, lanes cover a contiguous 4KB span
        float4* dst = (float4*)&g_T[(size_t)v * H_DIM];
#pragma unroll
        for (int j = 0; j < 8; j++)
            dst[j] = make_float4(out[4 * j], out[4 * j + 1],
                                 out[4 * j + 2], out[4 * j + 3]);
    }
}

// ---------------------------------------------------------------------------
// Kernel B: per batch row b:
//   s[h]   = sum_{l<L} T[x[b][l]][h]
//   hval   = relu(s[h] / len[b] + b1[h])
//   out[c] = b2[c] + sum_h hval * W2[h][c]
// One warp per batch row, lane = h. 4-way split accumulators for MLP.
// ---------------------------------------------------------------------------
__global__ __launch_bounds__(256)
void gather_mlp_kernel(const int* __restrict__ x,
                       const int* __restrict__ lengths,
                       const float* __restrict__ b1,
                       const float* __restrict__ W2,
                       const float* __restrict__ b2,
                       float* __restrict__ out) {
    const int lane = threadIdx.x & 31;
    const int wid  = threadIdx.x >> 5;
    const int b    = blockIdx.x * 8 + wid;
    if (b >= B_BATCH) return;

    const int* __restrict__ xr = x + (size_t)b * L_SEQ;

    float acc0 = 0.f, acc1 = 0.f, acc2 = 0.f, acc3 = 0.f;
#pragma unroll 2
    for (int l = 0; l < L_SEQ; l += 4) {
        int i0 = __ldg(&xr[l + 0]);
        int i1 = __ldg(&xr[l + 1]);
        int i2 = __ldg(&xr[l + 2]);
        int i3 = __ldg(&xr[l + 3]);
        acc0 += __ldg(&g_T[(size_t)i0 * H_DIM + lane]);
        acc1 += __ldg(&g_T[(size_t)i1 * H_DIM + lane]);
        acc2 += __ldg(&g_T[(size_t)i2 * H_DIM + lane]);
        acc3 += __ldg(&g_T[(size_t)i3 * H_DIM + lane]);
    }
    float s = (acc0 + acc1) + (acc2 + acc3);

    float len  = (float)__ldg(&lengths[b]);
    float hval = fmaxf(s / len + __ldg(&b1[lane]), 0.0f);

    float p0 = hval * __ldg(&W2[lane * C_DIM + 0]);
    float p1 = hval * __ldg(&W2[lane * C_DIM + 1]);
    float p2 = hval * __ldg(&W2[lane * C_DIM + 2]);
#pragma unroll
    for (int off = 16; off; off >>= 1) {
        p0 += __shfl_down_sync(0xffffffffu, p0, off);
        p1 += __shfl_down_sync(0xffffffffu, p1, off);
        p2 += __shfl_down_sync(0xffffffffu, p2, off);
    }
    if (lane == 0) {
        out[b * C_DIM + 0] = p0 + __ldg(&b2[0]);
        out[b * C_DIM + 1] = p1 + __ldg(&b2[1]);
        out[b * C_DIM + 2] = p2 + __ldg(&b2[2]);
    }
}

// ---------------------------------------------------------------------------
// Launch: inputs in metadata order: x, lengths, emb_table, W1, b1, W2, b2
// ---------------------------------------------------------------------------
extern "C" void kernel_launch(void* const* d_in, const int* in_sizes, int n_in,
                              void* d_out, int out_size) {
    const int*   x       = (const int*)d_in[0];
    const int*   lengths = (const int*)d_in[1];
    const float* emb     = (const float*)d_in[2];
    const float* W1      = (const float*)d_in[3];
    const float* b1      = (const float*)d_in[4];
    const float* W2      = (const float*)d_in[5];
    const float* b2      = (const float*)d_in[6];
    float*       out     = (float*)d_out;

    (void)in_sizes; (void)n_in; (void)out_size;

    gemm_T_kernel<<<(V_TOK + TOK_PER_CTA - 1) / TOK_PER_CTA, TOK_PER_CTA>>>(emb, W1);
    gather_mlp_kernel<<<(B_BATCH + 7) / 8, 256>>>(x, lengths, b1, W2, b2, out);
}

// round 6
// speedup vs baseline: 1.0080x; 1.0080x over previous
#include <cuda_runtime.h>
#include <stdint.h>

// Shapes fixed by the problem definition.
#define V_TOK   50000
#define D_DIM   300
#define H_DIM   32
#define C_DIM   3
#define B_BATCH 2048
#define L_SEQ   200

// Scratch: T = emb_table @ W1, [V_TOK, H_DIM] fp32 (6.4 MB). __device__ global
// array (no dynamic allocation allowed anywhere).
__device__ float g_T[V_TOK * H_DIM];

// ---------------------------------------------------------------------------
// Kernel A: T[v][h] = sum_d emb[v][d] * W1[d][h]
// One thread per token. D processed in chunks of DC staged through SMEM
// (coalesced global loads), W1 chunk staged in SMEM (broadcast LDS.64 reads).
// Inner product uses packed fma.rn.f32x2 (2 MACs / instr on the fp32 pipe).
// ---------------------------------------------------------------------------
#define TOK_PER_CTA 128
#define DC 60   // 300 = 5 * 60

__global__ __launch_bounds__(TOK_PER_CTA)
void gemm_T_kernel(const float* __restrict__ emb, const float* __restrict__ W1) {
    __shared__ float a_stage[TOK_PER_CTA][DC + 1];        // +1 pad: conflict-free column reads
    __shared__ __align__(16) float w_stage[DC][H_DIM];    // rows 128B-aligned -> LDS.64 ok

    const int tid  = threadIdx.x;
    const int lane = tid & 31;
    const int wid  = tid >> 5;
    const int v0   = blockIdx.x * TOK_PER_CTA;
    const int v    = v0 + tid;

    // 16 packed f32x2 accumulators = 32 fp32 outputs
    unsigned long long acc[16];
#pragma unroll
    for (int i = 0; i < 16; i++) acc[i] = 0ULL;   // bit pattern of (0.0f, 0.0f)

    for (int d0 = 0; d0 < D_DIM; d0 += DC) {
        __syncthreads();
        // Stage W1 chunk: contiguous DC*H region starting at d0*H
        for (int i = tid; i < DC * H_DIM; i += TOK_PER_CTA)
            ((float*)w_stage)[i] = W1[d0 * H_DIM + i];
        // Stage emb rows for this CTA's tokens (coalesced: warp reads a row slice)
        for (int r = wid; r < TOK_PER_CTA; r += (TOK_PER_CTA / 32)) {
            int vv = v0 + r;
            if (vv < V_TOK) {
                for (int d = lane; d < DC; d += 32)
                    a_stage[r][d] = emb[vv * D_DIM + d0 + d];
            }
        }
        __syncthreads();

        if (v < V_TOK) {
#pragma unroll 4
            for (int k = 0; k < DC; k++) {
                float a = a_stage[tid][k];
                unsigned long long a2;
                asm("mov.b64 %0, {%1, %1};" : "=l"(a2) : "f"(a));
                const unsigned long long* wrow =
                    (const unsigned long long*)&w_stage[k][0];
#pragma unroll
                for (int hp = 0; hp < 16; hp++) {
                    asm("fma.rn.f32x2 %0, %1, %2, %0;"
                        : "+l"(acc[hp]) : "l"(a2), "l"(wrow[hp]));
                }
            }
        }
    }

    if (v < V_TOK) {
        float out[H_DIM];
#pragma unroll
        for (int hp = 0; hp < 16; hp++) {
            unsigned int lo, hi;
            asm("mov.b64 {%0, %1}, %2;" : "=r"(lo), "=r"(hi) : "l"(acc[hp]));
            out[2 * hp]     = __uint_as_float(lo);
            out[2 * hp + 1] = __uint_as_float(hi);
        }
        // Row is 128B and 16B-aligned: 8x STG.128, lanes cover a contiguous 4KB span
        float4* dst = (float4*)&g_T[(size_t)v * H_DIM];
#pragma unroll
        for (int j = 0; j < 8; j++)
            dst[j] = make_float4(out[4 * j], out[4 * j + 1],
                                 out[4 * j + 2], out[4 * j + 3]);
    }
}

// ---------------------------------------------------------------------------
// Kernel B: per batch row b:
//   s[h]   = sum_{l<L} T[x[b][l]][h]
//   hval   = relu(s[h] / len[b] + b1[h])
//   out[c] = b2[c] + sum_h hval * W2[h][c]
// One warp per batch row, lane = h. 4-way split accumulators for MLP.
// ---------------------------------------------------------------------------
__global__ __launch_bounds__(256)
void gather_mlp_kernel(const int* __restrict__ x,
                       const int* __restrict__ lengths,
                       const float* __restrict__ b1,
                       const float* __restrict__ W2,
                       const float* __restrict__ b2,
                       float* __restrict__ out) {
    const int lane = threadIdx.x & 31;
    const int wid  = threadIdx.x >> 5;
    const int b    = blockIdx.x * 8 + wid;
    if (b >= B_BATCH) return;

    const int* __restrict__ xr = x + (size_t)b * L_SEQ;

    float acc0 = 0.f, acc1 = 0.f, acc2 = 0.f, acc3 = 0.f;
#pragma unroll 2
    for (int l = 0; l < L_SEQ; l += 4) {
        int i0 = __ldg(&xr[l + 0]);
        int i1 = __ldg(&xr[l + 1]);
        int i2 = __ldg(&xr[l + 2]);
        int i3 = __ldg(&xr[l + 3]);
        acc0 += __ldg(&g_T[(size_t)i0 * H_DIM + lane]);
        acc1 += __ldg(&g_T[(size_t)i1 * H_DIM + lane]);
        acc2 += __ldg(&g_T[(size_t)i2 * H_DIM + lane]);
        acc3 += __ldg(&g_T[(size_t)i3 * H_DIM + lane]);
    }
    float s = (acc0 + acc1) + (acc2 + acc3);

    float len  = (float)__ldg(&lengths[b]);
    float hval = fmaxf(s / len + __ldg(&b1[lane]), 0.0f);

    float p0 = hval * __ldg(&W2[lane * C_DIM + 0]);
    float p1 = hval * __ldg(&W2[lane * C_DIM + 1]);
    float p2 = hval * __ldg(&W2[lane * C_DIM + 2]);
#pragma unroll
    for (int off = 16; off; off >>= 1) {
        p0 += __shfl_down_sync(0xffffffffu, p0, off);
        p1 += __shfl_down_sync(0xffffffffu, p1, off);
        p2 += __shfl_down_sync(0xffffffffu, p2, off);
    }
    if (lane == 0) {
        out[b * C_DIM + 0] = p0 + __ldg(&b2[0]);
        out[b * C_DIM + 1] = p1 + __ldg(&b2[1]);
        out[b * C_DIM + 2] = p2 + __ldg(&b2[2]);
    }
}

// ---------------------------------------------------------------------------
// Launch: inputs in metadata order: x, lengths, emb_table, W1, b1, W2, b2
// ---------------------------------------------------------------------------
extern "C" void kernel_launch(void* const* d_in, const int* in_sizes, int n_in,
                              void* d_out, int out_size) {
    const int*   x       = (const int*)d_in[0];
    const int*   lengths = (const int*)d_in[1];
    const float* emb     = (const float*)d_in[2];
    const float* W1      = (const float*)d_in[3];
    const float* b1      = (const float*)d_in[4];
    const float* W2      = (const float*)d_in[5];
    const float* b2      = (const float*)d_in[6];
    float*       out     = (float*)d_out;

    (void)in_sizes; (void)n_in; (void)out_size;

    gemm_T_kernel<<<(V_TOK + TOK_PER_CTA - 1) / TOK_PER_CTA, TOK_PER_CTA>>>(emb, W1);
    gather_mlp_kernel<<<(B_BATCH + 7) / 8, 256>>>(x, lengths, b1, W2, b2, out);
}